// round 1
// baseline (speedup 1.0000x reference)
#include <cuda_runtime.h>
#include <cstdint>
#include <cstddef>

#define TT  512
#define BSZ 64
#define IND 1024
#define HD  256
#define G3  768   // 3*HD

// Scratch (static __device__ — no allocations allowed)
__device__ float g_gx[(size_t)2 * TT * BSZ * G3];  // pre-activations per direction (bih folded in)
__device__ float g_ys[(size_t)2 * TT * BSZ * HD];  // per-step hidden outputs per direction

// ---------------- f32x2 packed helpers ----------------
__device__ __forceinline__ unsigned long long pk2(float x, float y) {
    unsigned long long r;
    asm("mov.b64 %0, {%1, %2};" : "=l"(r) : "f"(x), "f"(y));
    return r;
}
__device__ __forceinline__ void upk2(unsigned long long v, float& x, float& y) {
    asm("mov.b64 {%0, %1}, %2;" : "=f"(x), "=f"(y) : "l"(v));
}
__device__ __forceinline__ void ffma2(unsigned long long& d, unsigned long long a, unsigned long long b) {
    asm("fma.rn.f32x2 %0, %1, %2, %0;" : "+l"(d) : "l"(a), "l"(b));
}

// =====================================================================
// Kernel A: gx[d][t][b][g] = src[t' (rev for bwd)][b][:] . Wih_d[g][:] + bih_d[g]
// GEMM M=32768, N=768, K=1024 per direction. Tile 128x128x16, 256 thr, 8x8 micro.
// =====================================================================
__global__ void __launch_bounds__(256) gx_gemm(
    const float* __restrict__ src,
    const float* __restrict__ Wih_f, const float* __restrict__ bih_f,
    const float* __restrict__ Wih_b, const float* __restrict__ bih_b)
{
    const int d = blockIdx.z;
    const float* __restrict__ Wih = d ? Wih_b : Wih_f;
    const float* __restrict__ bih = d ? bih_b : bih_f;
    const int m0 = blockIdx.x * 128;
    const int n0 = blockIdx.y * 128;

    __shared__ float As[16][132];  // [k][m]
    __shared__ float Bs[16][132];  // [k][n]

    const int tid = threadIdx.x;
    const int tx = tid & 15;   // 16 col-groups of 8
    const int ty = tid >> 4;   // 16 row-groups of 8

    unsigned long long acc[8][4];
#pragma unroll
    for (int i = 0; i < 8; i++)
#pragma unroll
        for (int j = 0; j < 4; j++) acc[i][j] = 0ull;

    for (int kt = 0; kt < IND; kt += 16) {
#pragma unroll
        for (int i = 0; i < 2; i++) {
            int idx = tid + i * 256;          // 0..511
            int mi  = idx >> 2;               // 0..127
            int ki  = (idx & 3) << 2;         // 0,4,8,12
            int m   = m0 + mi;
            int tt  = m >> 6, bb = m & 63;
            int srow = d ? ((TT - 1 - tt) * BSZ + bb) : m;
            float4 v = *(const float4*)(src + (size_t)srow * IND + kt + ki);
            As[ki + 0][mi] = v.x; As[ki + 1][mi] = v.y;
            As[ki + 2][mi] = v.z; As[ki + 3][mi] = v.w;
            float4 wv = *(const float4*)(Wih + (size_t)(n0 + mi) * IND + kt + ki);
            Bs[ki + 0][mi] = wv.x; Bs[ki + 1][mi] = wv.y;
            Bs[ki + 2][mi] = wv.z; Bs[ki + 3][mi] = wv.w;
        }
        __syncthreads();
#pragma unroll
        for (int k = 0; k < 16; k++) {
            float4 a0 = *(const float4*)&As[k][ty * 8];
            float4 a1 = *(const float4*)&As[k][ty * 8 + 4];
            ulonglong2 b0 = *(const ulonglong2*)&Bs[k][tx * 8];
            ulonglong2 b1 = *(const ulonglong2*)&Bs[k][tx * 8 + 4];
            float a[8] = {a0.x, a0.y, a0.z, a0.w, a1.x, a1.y, a1.z, a1.w};
            unsigned long long bb2[4] = {b0.x, b0.y, b1.x, b1.y};
#pragma unroll
            for (int i = 0; i < 8; i++) {
                unsigned long long ad = pk2(a[i], a[i]);
#pragma unroll
                for (int j = 0; j < 4; j++) ffma2(acc[i][j], ad, bb2[j]);
            }
        }
        __syncthreads();
    }

#pragma unroll
    for (int i = 0; i < 8; i++) {
        int m = m0 + ty * 8 + i;
        float* op = g_gx + ((size_t)d * TT * BSZ + m) * G3 + n0 + tx * 8;
#pragma unroll
        for (int j = 0; j < 4; j++) {
            float x, y;
            upk2(acc[i][j], x, y);
            int n = n0 + tx * 8 + j * 2;
            float2 o = make_float2(x + bih[n], y + bih[n + 1]);
            *(float2*)(op + j * 2) = o;
        }
    }
}

// =====================================================================
// Kernel B: GRU recurrence, persistent cluster kernel.
// 128 CTAs = 16 clusters of 8. cluster -> (direction, batch-group of 8).
// CTA rank -> 32 hidden units (x3 gates = 96 Whh rows, kept in registers,
// K-sliced 32 per warp). h replicated to all peers via DSMEM each step.
// =====================================================================
__global__ void __launch_bounds__(256, 1) __cluster_dims__(8, 1, 1)
gru_rec(const float* __restrict__ Whh_f, const float* __restrict__ bhh_f,
        const float* __restrict__ Whh_b, const float* __restrict__ bhh_b)
{
    __shared__ float h_sm[2][8][HD];        // double-buffered h, 8 batches x 256 units
    __shared__ float red[8][8][3][32];      // [warp(kslice)][batch][gate][lane]

    const int rank = blockIdx.x & 7;        // hidden-unit chunk
    const int cid  = blockIdx.x >> 3;
    const int d    = cid >> 3;              // direction
    const int bg   = cid & 7;               // batch group (8 batches)

    const float* __restrict__ Whh = d ? Whh_b : Whh_f;
    const float* __restrict__ bhh = d ? bhh_b : bhh_f;

    const int tid = threadIdx.x;
    const int w   = tid >> 5;               // warp = K-slice (phase 2) = batch (phase 3)
    const int l   = tid & 31;               // lane = local unit
    const int j   = rank * 32 + l;          // global hidden unit
    const int kb  = w * 32;                 // K-slice base

    // Whh rows {j, H+j, 2H+j}, cols [kb, kb+32) -> 48 f32x2 registers
    unsigned long long Wr[16], Wz[16], Wn[16];
#pragma unroll
    for (int q = 0; q < 16; q++) {
        Wr[q] = *(const unsigned long long*)(Whh + (size_t)j * HD + kb + 2 * q);
        Wz[q] = *(const unsigned long long*)(Whh + (size_t)(HD + j) * HD + kb + 2 * q);
        Wn[q] = *(const unsigned long long*)(Whh + (size_t)(2 * HD + j) * HD + kb + 2 * q);
    }
    const float br = bhh[j], bz = bhh[HD + j], bn = bhh[2 * HD + j];

    // output-phase indices: this thread owns (batch=w, unit=j)
    size_t gx_ix = ((size_t)d * TT * BSZ + (size_t)(bg * 8 + w)) * G3 + j;
    size_t ys_ix = ((size_t)d * TT * BSZ + (size_t)(bg * 8 + w)) * HD + j;

    // h0 = 0
    for (int i = tid; i < 8 * HD; i += 256) (&h_sm[0][0][0])[i] = 0.f;
    __syncthreads();
    asm volatile("barrier.cluster.arrive.aligned;" ::: "memory");
    asm volatile("barrier.cluster.wait.aligned;" ::: "memory");

    uint32_t haddr_base;
    asm("{ .reg .u64 t; cvta.to.shared.u64 t, %1; cvt.u32.u64 %0, t; }"
        : "=r"(haddr_base) : "l"(&h_sm[0][0][0]));

    int cur = 0;
    for (int t = 0; t < TT; ++t) {
        // prefetch this step's gx (consumed ~1500 cycles later)
        float gxr = g_gx[gx_ix];
        float gxz = g_gx[gx_ix + HD];
        float gxn = g_gx[gx_ix + 2 * HD];

        // phase 2: matvec partials over this warp's K-slice, all 8 batches
#pragma unroll 1
        for (int b = 0; b < 8; b++) {
            const ulonglong2* hp = (const ulonglong2*)&h_sm[cur][b][kb];
            unsigned long long ar0 = 0, ar1 = 0, az0 = 0, az1 = 0, an0 = 0, an1 = 0;
#pragma unroll
            for (int q = 0; q < 8; q++) {
                ulonglong2 hv = hp[q];  // broadcast across warp
                ffma2(ar0, Wr[2 * q], hv.x); ffma2(ar1, Wr[2 * q + 1], hv.y);
                ffma2(az0, Wz[2 * q], hv.x); ffma2(az1, Wz[2 * q + 1], hv.y);
                ffma2(an0, Wn[2 * q], hv.x); ffma2(an1, Wn[2 * q + 1], hv.y);
            }
            float x0, y0, x1, y1;
            upk2(ar0, x0, y0); upk2(ar1, x1, y1); red[w][b][0][l] = x0 + y0 + x1 + y1;
            upk2(az0, x0, y0); upk2(az1, x1, y1); red[w][b][1][l] = x0 + y0 + x1 + y1;
            upk2(an0, x0, y0); upk2(an1, x1, y1); red[w][b][2][l] = x0 + y0 + x1 + y1;
        }
        __syncthreads();

        // phase 3: reduce 8 K-slices, gates, h update (thread owns batch w, unit j)
        float sr = br, sz = bz, sn = bn;
#pragma unroll
        for (int w2 = 0; w2 < 8; w2++) {
            sr += red[w2][w][0][l];
            sz += red[w2][w][1][l];
            sn += red[w2][w][2][l];
        }
        float r = 1.f / (1.f + expf(-(gxr + sr)));
        float z = 1.f / (1.f + expf(-(gxz + sz)));
        float n = tanhf(gxn + r * sn);
        float hprev = h_sm[cur][w][j];
        float hnew  = n + z * (hprev - n);

        g_ys[ys_ix] = hnew;

        // broadcast hnew into every peer's h_sm[cur^1][w][j]
        uint32_t la = haddr_base + (uint32_t)((((cur ^ 1) * 8 + w) * HD + j) * 4);
#pragma unroll
        for (int p = 0; p < 8; p++) {
            uint32_t ra;
            asm volatile("mapa.shared::cluster.u32 %0, %1, %2;" : "=r"(ra) : "r"(la), "r"(p));
            asm volatile("st.shared::cluster.f32 [%0], %1;" :: "r"(ra), "f"(hnew) : "memory");
        }
        asm volatile("barrier.cluster.arrive.aligned;" ::: "memory");
        asm volatile("barrier.cluster.wait.aligned;" ::: "memory");

        cur ^= 1;
        gx_ix += (size_t)BSZ * G3;
        ys_ix += (size_t)BSZ * HD;
    }
}

// =====================================================================
// Kernel C: outputs[t][b][o] = [ysf[t][b]|ysb[T-1-t][b]] . Wout[o][:] + bout[o]
// GEMM M=32768, N=256, K=512. Tile 128x64x16, 256 thr, 4x8 micro.
// =====================================================================
__global__ void __launch_bounds__(256) out_gemm(
    const float* __restrict__ Wout, const float* __restrict__ bout,
    float* __restrict__ out)
{
    const int m0 = blockIdx.x * 128;
    const int n0 = blockIdx.y * 64;

    __shared__ float As[16][132];
    __shared__ float Bs[16][68];

    const int tid = threadIdx.x;
    const int tx = tid & 7;    // 8 col-groups of 8
    const int ty = tid >> 3;   // 32 row-groups of 4

    unsigned long long acc[4][4];
#pragma unroll
    for (int i = 0; i < 4; i++)
#pragma unroll
        for (int j = 0; j < 4; j++) acc[i][j] = 0ull;

    for (int kt = 0; kt < 2 * HD; kt += 16) {
#pragma unroll
        for (int i = 0; i < 2; i++) {
            int idx = tid + i * 256;
            int mi = idx >> 2, ki = (idx & 3) << 2;
            int m = m0 + mi;
            size_t aoff;
            if (kt < HD) {
                aoff = (size_t)m * HD + kt + ki;  // forward: m == t*64+b contiguous
            } else {
                int tt = m >> 6, bb = m & 63;
                aoff = (size_t)TT * BSZ * HD +
                       ((size_t)(TT - 1 - tt) * BSZ + bb) * HD + (kt + ki - HD);
            }
            float4 v = *(const float4*)(g_ys + aoff);
            As[ki + 0][mi] = v.x; As[ki + 1][mi] = v.y;
            As[ki + 2][mi] = v.z; As[ki + 3][mi] = v.w;
        }
        {
            int ni = tid >> 2, ki = (tid & 3) << 2;  // 64 x 16
            float4 wv = *(const float4*)(Wout + (size_t)(n0 + ni) * (2 * HD) + kt + ki);
            Bs[ki + 0][ni] = wv.x; Bs[ki + 1][ni] = wv.y;
            Bs[ki + 2][ni] = wv.z; Bs[ki + 3][ni] = wv.w;
        }
        __syncthreads();
#pragma unroll
        for (int k = 0; k < 16; k++) {
            float4 a0 = *(const float4*)&As[k][ty * 4];
            ulonglong2 b0 = *(const ulonglong2*)&Bs[k][tx * 8];
            ulonglong2 b1 = *(const ulonglong2*)&Bs[k][tx * 8 + 4];
            float a[4] = {a0.x, a0.y, a0.z, a0.w};
            unsigned long long bb2[4] = {b0.x, b0.y, b1.x, b1.y};
#pragma unroll
            for (int i = 0; i < 4; i++) {
                unsigned long long ad = pk2(a[i], a[i]);
#pragma unroll
                for (int j = 0; j < 4; j++) ffma2(acc[i][j], ad, bb2[j]);
            }
        }
        __syncthreads();
    }

#pragma unroll
    for (int i = 0; i < 4; i++) {
        int m = m0 + ty * 4 + i;
        float* op = out + (size_t)m * HD + n0 + tx * 8;
#pragma unroll
        for (int j = 0; j < 4; j++) {
            float x, y;
            upk2(acc[i][j], x, y);
            int n = n0 + tx * 8 + j * 2;
            float2 o = make_float2(x + bout[n], y + bout[n + 1]);
            *(float2*)(op + j * 2) = o;
        }
    }
}

// =====================================================================
// Kernel D: hidden[b][o] = tanh([h_f[b]|h_b[b]] . Whid[o][:] + bhid[o])
// =====================================================================
__global__ void __launch_bounds__(256) hid_kernel(
    const float* __restrict__ Whid, const float* __restrict__ bhid,
    float* __restrict__ hid)
{
    const int b = blockIdx.x;
    const int o = threadIdx.x;
    __shared__ float hc[2 * HD];
    for (int k = threadIdx.x; k < 2 * HD; k += 256) {
        hc[k] = (k < HD)
            ? g_ys[((size_t)(TT - 1) * BSZ + b) * HD + k]
            : g_ys[(size_t)TT * BSZ * HD + ((size_t)(TT - 1) * BSZ + b) * HD + (k - HD)];
    }
    __syncthreads();
    float acc = bhid[o];
    const float4* wp = (const float4*)(Whid + (size_t)o * (2 * HD));
    const float4* hp = (const float4*)hc;
#pragma unroll 4
    for (int q = 0; q < (2 * HD) / 4; q++) {
        float4 wv = wp[q], hv = hp[q];
        acc += wv.x * hv.x + wv.y * hv.y + wv.z * hv.z + wv.w * hv.w;
    }
    hid[(size_t)b * HD + o] = tanhf(acc);
}

// =====================================================================
extern "C" void kernel_launch(void* const* d_in, const int* in_sizes, int n_in,
                              void* d_out, int out_size)
{
    const float* src   = (const float*)d_in[0];
    const float* Wih_f = (const float*)d_in[1];
    const float* Whh_f = (const float*)d_in[2];
    const float* bih_f = (const float*)d_in[3];
    const float* bhh_f = (const float*)d_in[4];
    const float* Wih_b = (const float*)d_in[5];
    const float* Whh_b = (const float*)d_in[6];
    const float* bih_b = (const float*)d_in[7];
    const float* bhh_b = (const float*)d_in[8];
    const float* Wout  = (const float*)d_in[9];
    const float* bout  = (const float*)d_in[10];
    const float* Whid  = (const float*)d_in[11];
    const float* bhid  = (const float*)d_in[12];
    float* out = (float*)d_out;

    gx_gemm<<<dim3(TT * BSZ / 128, G3 / 128, 2), 256>>>(src, Wih_f, bih_f, Wih_b, bih_b);
    gru_rec<<<128, 256>>>(Whh_f, bhh_f, Whh_b, bhh_b);
    out_gemm<<<dim3(TT * BSZ / 128, HD / 64), 256>>>(Wout, bout, out);
    hid_kernel<<<BSZ, 256>>>(Whid, bhid, out + (size_t)TT * BSZ * HD);
}

// round 5
// speedup vs baseline: 1.1842x; 1.1842x over previous
#include <cuda_runtime.h>
#include <cuda_bf16.h>
#include <cstdint>
#include <cstddef>

#define TT  512
#define BSZ 64
#define IND 1024
#define HD  256
#define G3  768   // 3*HD

// ---------------- scratch (static __device__ — no allocations allowed) ----------------
__device__ float g_gx[(size_t)2 * TT * BSZ * G3];  // pre-activations per direction (bih folded in)
__device__ float g_ys[(size_t)2 * TT * BSZ * HD];  // per-step hidden outputs per direction

__device__ __align__(16) __nv_bfloat16 g_src_hi[(size_t)TT * BSZ * IND];
__device__ __align__(16) __nv_bfloat16 g_src_lo[(size_t)TT * BSZ * IND];
__device__ __align__(16) __nv_bfloat16 g_wih_hi[(size_t)2 * G3 * IND];
__device__ __align__(16) __nv_bfloat16 g_wih_lo[(size_t)2 * G3 * IND];

// ---------------- helpers ----------------
__device__ __forceinline__ uint32_t smem_u32(const void* p) {
    uint32_t a;
    asm("{ .reg .u64 t; cvta.to.shared.u64 t, %1; cvt.u32.u64 %0, t; }" : "=r"(a) : "l"(p));
    return a;
}

#define CP16(dst, src) \
    asm volatile("cp.async.cg.shared.global [%0], [%1], 16;" :: "r"(dst), "l"(src))
#define CP_COMMIT() asm volatile("cp.async.commit_group;" ::: "memory")
#define CP_WAIT(n)  asm volatile("cp.async.wait_group %0;" :: "n"(n) : "memory")

#define LDSM4(R, addr) \
    asm volatile("ldmatrix.sync.aligned.m8n8.x4.shared.b16 {%0,%1,%2,%3}, [%4];" \
                 : "=r"((R)[0]), "=r"((R)[1]), "=r"((R)[2]), "=r"((R)[3]) : "r"(addr))

#define MMA16816(C, A, B0, B1) \
    asm volatile("mma.sync.aligned.m16n8k16.row.col.f32.bf16.bf16.f32 " \
                 "{%0,%1,%2,%3}, {%4,%5,%6,%7}, {%8,%9}, {%0,%1,%2,%3};" \
                 : "+f"((C)[0]), "+f"((C)[1]), "+f"((C)[2]), "+f"((C)[3]) \
                 : "r"((A)[0]), "r"((A)[1]), "r"((A)[2]), "r"((A)[3]), "r"(B0), "r"(B1))

// ---------------- f32x2 packed helpers ----------------
__device__ __forceinline__ unsigned long long pk2(float x, float y) {
    unsigned long long r;
    asm("mov.b64 %0, {%1, %2};" : "=l"(r) : "f"(x), "f"(y));
    return r;
}
__device__ __forceinline__ void upk2(unsigned long long v, float& x, float& y) {
    asm("mov.b64 {%0, %1}, %2;" : "=f"(x), "=f"(y) : "l"(v));
}
__device__ __forceinline__ void ffma2(unsigned long long& d, unsigned long long a, unsigned long long b) {
    asm("fma.rn.f32x2 %0, %1, %2, %0;" : "+l"(d) : "l"(a), "l"(b));
}

// =====================================================================
// Kernel 0: split fp32 -> (hi, lo) bf16 pair. which: 0=src, 1=Wih_f, 2=Wih_b
// =====================================================================
__global__ void __launch_bounds__(256) split_bf16(const float* __restrict__ x, int which, int n)
{
    __nv_bfloat16* hi;
    __nv_bfloat16* lo;
    if (which == 0)      { hi = g_src_hi;                    lo = g_src_lo; }
    else if (which == 1) { hi = g_wih_hi;                    lo = g_wih_lo; }
    else                 { hi = g_wih_hi + (size_t)G3 * IND; lo = g_wih_lo + (size_t)G3 * IND; }

    int i = (blockIdx.x * 256 + threadIdx.x) * 4;
    if (i >= n) return;
    float4 v = *(const float4*)(x + i);
    __nv_bfloat16 h0 = __float2bfloat16_rn(v.x);
    __nv_bfloat16 h1 = __float2bfloat16_rn(v.y);
    __nv_bfloat16 h2 = __float2bfloat16_rn(v.z);
    __nv_bfloat16 h3 = __float2bfloat16_rn(v.w);
    __nv_bfloat16 l0 = __float2bfloat16_rn(v.x - __bfloat162float(h0));
    __nv_bfloat16 l1 = __float2bfloat16_rn(v.y - __bfloat162float(h1));
    __nv_bfloat16 l2 = __float2bfloat16_rn(v.z - __bfloat162float(h2));
    __nv_bfloat16 l3 = __float2bfloat16_rn(v.w - __bfloat162float(h3));
    *(__nv_bfloat162*)(hi + i)     = __nv_bfloat162(h0, h1);
    *(__nv_bfloat162*)(hi + i + 2) = __nv_bfloat162(h2, h3);
    *(__nv_bfloat162*)(lo + i)     = __nv_bfloat162(l0, l1);
    *(__nv_bfloat162*)(lo + i + 2) = __nv_bfloat162(l2, l3);
}

// =====================================================================
// Kernel A: gx via mma.sync (HMMA) bf16 split 3-MMA.
// CTA tile 128x128, K chunks of 32, cp.async double buffered.
// 8 warps as 4(m) x 2(n); warp tile 32x64 = 2x8 m16n8k16 tiles.
// SMEM rows padded to 40 bf16 (80B) -> conflict-free ldmatrix.
// =====================================================================
#define GX_ROWB      80                  // bytes per SMEM row (40 bf16)
#define GX_MAT       (128 * GX_ROWB)     // 10240 bytes per matrix
#define GX_OFF_A_HI  0
#define GX_OFF_A_LO  (GX_MAT)
#define GX_OFF_B_HI  (2 * GX_MAT)
#define GX_OFF_B_LO  (3 * GX_MAT)
#define GX_STAGE     (4 * GX_MAT)        // 40960
#define GX_SMEM_TOTAL (2 * GX_STAGE)     // 81920

__global__ void __launch_bounds__(256) gx_mma(const float* __restrict__ bih_f,
                                              const float* __restrict__ bih_b)
{
    extern __shared__ char smem[];
    const uint32_t sbase = smem_u32(smem);
    const int tid = threadIdx.x;
    const int wid = tid >> 5;
    const int lid = tid & 31;
    const int wm  = wid >> 1;      // 0..3
    const int wn  = wid & 1;       // 0..1

    const int n0 = blockIdx.x * 128;   // n fastest -> B tiles L2-resident, A shared by 6 CTAs
    const int m0 = blockIdx.y * 128;
    const int d  = blockIdx.z;

    const __nv_bfloat16* __restrict__ whi = g_wih_hi + (size_t)d * G3 * IND;
    const __nv_bfloat16* __restrict__ wlo = g_wih_lo + (size_t)d * G3 * IND;
    const float* __restrict__ bih = d ? bih_b : bih_f;

    // ---- per-thread load mapping: row = tid&127, 16B chunk sub in {sub0, sub0+2} ----
    const int rowL = tid & 127;
    const int sub0 = tid >> 7;      // 0 or 1
    int mA = m0 + rowL;
    int srow = d ? ((TT - 1 - (mA >> 6)) * BSZ + (mA & 63)) : mA;
    const __nv_bfloat16* gA_hi = g_src_hi + (size_t)srow * IND;
    const __nv_bfloat16* gA_lo = g_src_lo + (size_t)srow * IND;
    const __nv_bfloat16* gB_hi = whi + (size_t)(n0 + rowL) * IND;
    const __nv_bfloat16* gB_lo = wlo + (size_t)(n0 + rowL) * IND;
    const uint32_t soRow = (uint32_t)(rowL * GX_ROWB);

    // ---- per-lane ldmatrix offsets ----
    const int blk = lid >> 3, rr = lid & 7;
    const uint32_t aoff = (uint32_t)(((wm * 32 + (blk & 1) * 8 + rr) * 40 + (blk >> 1) * 8) * 2);
    const uint32_t boff = (uint32_t)(((wn * 64 + (blk & 1) * 8 + rr) * 40 + (blk >> 1) * 8) * 2);

    float acc[2][8][4];
#pragma unroll
    for (int i = 0; i < 2; i++)
#pragma unroll
        for (int j = 0; j < 8; j++)
#pragma unroll
            for (int q = 0; q < 4; q++) acc[i][j][q] = 0.f;

    // ---- load chunk helper (kc: 0..31), stage in {0,1} ----
    auto load_chunk = [&](int kc, int stage) {
        const int kb = kc * 32;
        const uint32_t s0 = sbase + stage * GX_STAGE;
#pragma unroll
        for (int i = 0; i < 2; i++) {
            int sub = sub0 + 2 * i;
            uint32_t so = soRow + sub * 16;
            const int ge = kb + sub * 8;
            CP16(s0 + GX_OFF_A_HI + so, gA_hi + ge);
            CP16(s0 + GX_OFF_A_LO + so, gA_lo + ge);
            CP16(s0 + GX_OFF_B_HI + so, gB_hi + ge);
            CP16(s0 + GX_OFF_B_LO + so, gB_lo + ge);
        }
        CP_COMMIT();
    };

    load_chunk(0, 0);

    for (int kc = 0; kc < 32; kc++) {
        const int cur = kc & 1;
        if (kc < 31) load_chunk(kc + 1, cur ^ 1);
        if (kc < 31) { CP_WAIT(1); } else { CP_WAIT(0); }
        __syncthreads();

        const uint32_t s0 = sbase + cur * GX_STAGE;
#pragma unroll
        for (int ks = 0; ks < 2; ks++) {
            const uint32_t koff = ks * 32;   // 16 bf16 = 32 bytes
            uint32_t ah[2][4], al[2][4];
            LDSM4(ah[0], s0 + GX_OFF_A_HI + aoff + koff);
            LDSM4(ah[1], s0 + GX_OFF_A_HI + aoff + 16 * GX_ROWB + koff);
            LDSM4(al[0], s0 + GX_OFF_A_LO + aoff + koff);
            LDSM4(al[1], s0 + GX_OFF_A_LO + aoff + 16 * GX_ROWB + koff);
            uint32_t bh[4][4], bl[4][4];
#pragma unroll
            for (int p = 0; p < 4; p++) {
                LDSM4(bh[p], s0 + GX_OFF_B_HI + boff + p * 16 * GX_ROWB + koff);
                LDSM4(bl[p], s0 + GX_OFF_B_LO + boff + p * 16 * GX_ROWB + koff);
            }
#pragma unroll
            for (int tm = 0; tm < 2; tm++) {
#pragma unroll
                for (int tn = 0; tn < 8; tn++) {
                    const int p = tn >> 1, o = tn & 1;
                    MMA16816(acc[tm][tn], ah[tm], bh[p][o], bh[p][2 + o]);
                    MMA16816(acc[tm][tn], ah[tm], bl[p][o], bl[p][2 + o]);
                    MMA16816(acc[tm][tn], al[tm], bh[p][o], bh[p][2 + o]);
                }
            }
        }
        __syncthreads();
    }

    // ---- epilogue: direct register -> global stores, bias folded ----
    const int g  = lid >> 2;
    const int t4 = lid & 3;
    const size_t dbase = (size_t)d * TT * BSZ;
#pragma unroll
    for (int tm = 0; tm < 2; tm++) {
        int mr = m0 + wm * 32 + tm * 16 + g;
#pragma unroll
        for (int tn = 0; tn < 8; tn++) {
            int col = n0 + wn * 64 + tn * 8 + t4 * 2;
            float2 bv = *(const float2*)(bih + col);
            float2 v0 = make_float2(acc[tm][tn][0] + bv.x, acc[tm][tn][1] + bv.y);
            float2 v1 = make_float2(acc[tm][tn][2] + bv.x, acc[tm][tn][3] + bv.y);
            *(float2*)(g_gx + (dbase + mr) * G3 + col)     = v0;
            *(float2*)(g_gx + (dbase + mr + 8) * G3 + col) = v1;
        }
    }
}

// =====================================================================
// Kernel B: GRU recurrence, persistent cluster kernel (unchanged from R1 pass).
// =====================================================================
__global__ void __launch_bounds__(256, 1) __cluster_dims__(8, 1, 1)
gru_rec(const float* __restrict__ Whh_f, const float* __restrict__ bhh_f,
        const float* __restrict__ Whh_b, const float* __restrict__ bhh_b)
{
    __shared__ float h_sm[2][8][HD];
    __shared__ float red[8][8][3][32];

    const int rank = blockIdx.x & 7;
    const int cid  = blockIdx.x >> 3;
    const int d    = cid >> 3;
    const int bg   = cid & 7;

    const float* __restrict__ Whh = d ? Whh_b : Whh_f;
    const float* __restrict__ bhh = d ? bhh_b : bhh_f;

    const int tid = threadIdx.x;
    const int w   = tid >> 5;
    const int l   = tid & 31;
    const int j   = rank * 32 + l;
    const int kb  = w * 32;

    unsigned long long Wr[16], Wz[16], Wn[16];
#pragma unroll
    for (int q = 0; q < 16; q++) {
        Wr[q] = *(const unsigned long long*)(Whh + (size_t)j * HD + kb + 2 * q);
        Wz[q] = *(const unsigned long long*)(Whh + (size_t)(HD + j) * HD + kb + 2 * q);
        Wn[q] = *(const unsigned long long*)(Whh + (size_t)(2 * HD + j) * HD + kb + 2 * q);
    }
    const float br = bhh[j], bz = bhh[HD + j], bn = bhh[2 * HD + j];

    size_t gx_ix = ((size_t)d * TT * BSZ + (size_t)(bg * 8 + w)) * G3 + j;
    size_t ys_ix = ((size_t)d * TT * BSZ + (size_t)(bg * 8 + w)) * HD + j;

    for (int i = tid; i < 8 * HD; i += 256) (&h_sm[0][0][0])[i] = 0.f;
    __syncthreads();
    asm volatile("barrier.cluster.arrive.aligned;" ::: "memory");
    asm volatile("barrier.cluster.wait.aligned;" ::: "memory");

    uint32_t haddr_base;
    asm("{ .reg .u64 t; cvta.to.shared.u64 t, %1; cvt.u32.u64 %0, t; }"
        : "=r"(haddr_base) : "l"(&h_sm[0][0][0]));

    int cur = 0;
    for (int t = 0; t < TT; ++t) {
        float gxr = g_gx[gx_ix];
        float gxz = g_gx[gx_ix + HD];
        float gxn = g_gx[gx_ix + 2 * HD];

#pragma unroll 1
        for (int b = 0; b < 8; b++) {
            const ulonglong2* hp = (const ulonglong2*)&h_sm[cur][b][kb];
            unsigned long long ar0 = 0, ar1 = 0, az0 = 0, az1 = 0, an0 = 0, an1 = 0;
#pragma unroll
            for (int q = 0; q < 8; q++) {
                ulonglong2 hv = hp[q];
                ffma2(ar0, Wr[2 * q], hv.x); ffma2(ar1, Wr[2 * q + 1], hv.y);
                ffma2(az0, Wz[2 * q], hv.x); ffma2(az1, Wz[2 * q + 1], hv.y);
                ffma2(an0, Wn[2 * q], hv.x); ffma2(an1, Wn[2 * q + 1], hv.y);
            }
            float x0, y0, x1, y1;
            upk2(ar0, x0, y0); upk2(ar1, x1, y1); red[w][b][0][l] = x0 + y0 + x1 + y1;
            upk2(az0, x0, y0); upk2(az1, x1, y1); red[w][b][1][l] = x0 + y0 + x1 + y1;
            upk2(an0, x0, y0); upk2(an1, x1, y1); red[w][b][2][l] = x0 + y0 + x1 + y1;
        }
        __syncthreads();

        float sr = br, sz = bz, sn = bn;
#pragma unroll
        for (int w2 = 0; w2 < 8; w2++) {
            sr += red[w2][w][0][l];
            sz += red[w2][w][1][l];
            sn += red[w2][w][2][l];
        }
        float r = 1.f / (1.f + expf(-(gxr + sr)));
        float z = 1.f / (1.f + expf(-(gxz + sz)));
        float n = tanhf(gxn + r * sn);
        float hprev = h_sm[cur][w][j];
        float hnew  = n + z * (hprev - n);

        g_ys[ys_ix] = hnew;

        uint32_t la = haddr_base + (uint32_t)((((cur ^ 1) * 8 + w) * HD + j) * 4);
#pragma unroll
        for (int p = 0; p < 8; p++) {
            uint32_t ra;
            asm volatile("mapa.shared::cluster.u32 %0, %1, %2;" : "=r"(ra) : "r"(la), "r"(p));
            asm volatile("st.shared::cluster.f32 [%0], %1;" :: "r"(ra), "f"(hnew) : "memory");
        }
        asm volatile("barrier.cluster.arrive.aligned;" ::: "memory");
        asm volatile("barrier.cluster.wait.aligned;" ::: "memory");

        cur ^= 1;
        gx_ix += (size_t)BSZ * G3;
        ys_ix += (size_t)BSZ * HD;
    }
}

// =====================================================================
// Kernel C: outputs GEMM (fp32 FFMA2, unchanged)
// =====================================================================
__global__ void __launch_bounds__(256) out_gemm(
    const float* __restrict__ Wout, const float* __restrict__ bout,
    float* __restrict__ out)
{
    const int m0 = blockIdx.x * 128;
    const int n0 = blockIdx.y * 64;

    __shared__ float As[16][132];
    __shared__ float Bs[16][68];

    const int tid = threadIdx.x;
    const int tx = tid & 7;
    const int ty = tid >> 3;

    unsigned long long acc[4][4];
#pragma unroll
    for (int i = 0; i < 4; i++)
#pragma unroll
        for (int j = 0; j < 4; j++) acc[i][j] = 0ull;

    for (int kt = 0; kt < 2 * HD; kt += 16) {
#pragma unroll
        for (int i = 0; i < 2; i++) {
            int idx = tid + i * 256;
            int mi = idx >> 2, ki = (idx & 3) << 2;
            int m = m0 + mi;
            size_t aoff;
            if (kt < HD) {
                aoff = (size_t)m * HD + kt + ki;
            } else {
                int tt = m >> 6, bb = m & 63;
                aoff = (size_t)TT * BSZ * HD +
                       ((size_t)(TT - 1 - tt) * BSZ + bb) * HD + (kt + ki - HD);
            }
            float4 v = *(const float4*)(g_ys + aoff);
            As[ki + 0][mi] = v.x; As[ki + 1][mi] = v.y;
            As[ki + 2][mi] = v.z; As[ki + 3][mi] = v.w;
        }
        {
            int ni = tid >> 2, ki = (tid & 3) << 2;
            float4 wv = *(const float4*)(Wout + (size_t)(n0 + ni) * (2 * HD) + kt + ki);
            Bs[ki + 0][ni] = wv.x; Bs[ki + 1][ni] = wv.y;
            Bs[ki + 2][ni] = wv.z; Bs[ki + 3][ni] = wv.w;
        }
        __syncthreads();
#pragma unroll
        for (int k = 0; k < 16; k++) {
            float4 a0 = *(const float4*)&As[k][ty * 4];
            ulonglong2 b0 = *(const ulonglong2*)&Bs[k][tx * 8];
            ulonglong2 b1 = *(const ulonglong2*)&Bs[k][tx * 8 + 4];
            float a[4] = {a0.x, a0.y, a0.z, a0.w};
            unsigned long long bb2[4] = {b0.x, b0.y, b1.x, b1.y};
#pragma unroll
            for (int i = 0; i < 4; i++) {
                unsigned long long ad = pk2(a[i], a[i]);
#pragma unroll
                for (int j = 0; j < 4; j++) ffma2(acc[i][j], ad, bb2[j]);
            }
        }
        __syncthreads();
    }

#pragma unroll
    for (int i = 0; i < 4; i++) {
        int m = m0 + ty * 4 + i;
        float* op = out + (size_t)m * HD + n0 + tx * 8;
#pragma unroll
        for (int j = 0; j < 4; j++) {
            float x, y;
            upk2(acc[i][j], x, y);
            int n = n0 + tx * 8 + j * 2;
            float2 o = make_float2(x + bout[n], y + bout[n + 1]);
            *(float2*)(op + j * 2) = o;
        }
    }
}

// =====================================================================
// Kernel D: hidden projection (unchanged)
// =====================================================================
__global__ void __launch_bounds__(256) hid_kernel(
    const float* __restrict__ Whid, const float* __restrict__ bhid,
    float* __restrict__ hid)
{
    const int b = blockIdx.x;
    const int o = threadIdx.x;
    __shared__ float hc[2 * HD];
    for (int k = threadIdx.x; k < 2 * HD; k += 256) {
        hc[k] = (k < HD)
            ? g_ys[((size_t)(TT - 1) * BSZ + b) * HD + k]
            : g_ys[(size_t)TT * BSZ * HD + ((size_t)(TT - 1) * BSZ + b) * HD + (k - HD)];
    }
    __syncthreads();
    float acc = bhid[o];
    const float4* wp = (const float4*)(Whid + (size_t)o * (2 * HD));
    const float4* hp = (const float4*)hc;
#pragma unroll 4
    for (int q = 0; q < (2 * HD) / 4; q++) {
        float4 wv = wp[q], hv = hp[q];
        acc += wv.x * hv.x + wv.y * hv.y + wv.z * hv.z + wv.w * hv.w;
    }
    hid[(size_t)b * HD + o] = tanhf(acc);
}

// =====================================================================
extern "C" void kernel_launch(void* const* d_in, const int* in_sizes, int n_in,
                              void* d_out, int out_size)
{
    const float* src   = (const float*)d_in[0];
    const float* Wih_f = (const float*)d_in[1];
    const float* Whh_f = (const float*)d_in[2];
    const float* bih_f = (const float*)d_in[3];
    const float* bhh_f = (const float*)d_in[4];
    const float* Wih_b = (const float*)d_in[5];
    const float* Whh_b = (const float*)d_in[6];
    const float* bih_b = (const float*)d_in[7];
    const float* bhh_b = (const float*)d_in[8];
    const float* Wout  = (const float*)d_in[9];
    const float* bout  = (const float*)d_in[10];
    const float* Whid  = (const float*)d_in[11];
    const float* bhid  = (const float*)d_in[12];
    float* out = (float*)d_out;

    cudaFuncSetAttribute(gx_mma, cudaFuncAttributeMaxDynamicSharedMemorySize, GX_SMEM_TOTAL);

    {
        int n_src = TT * BSZ * IND;
        int n_w   = G3 * IND;
        split_bf16<<<(n_src / 4 + 255) / 256, 256>>>(src, 0, n_src);
        split_bf16<<<(n_w   / 4 + 255) / 256, 256>>>(Wih_f, 1, n_w);
        split_bf16<<<(n_w   / 4 + 255) / 256, 256>>>(Wih_b, 2, n_w);
    }

    gx_mma<<<dim3(G3 / 128, TT * BSZ / 128, 2), 256, GX_SMEM_TOTAL>>>(bih_f, bih_b);
    gru_rec<<<128, 256>>>(Whh_f, bhh_f, Whh_b, bhh_b);
    out_gemm<<<dim3(TT * BSZ / 128, HD / 64), 256>>>(Wout, bout, out);
    hid_kernel<<<BSZ, 256>>>(Whid, bhid, out + (size_t)TT * BSZ * HD);
}

// round 6
// speedup vs baseline: 1.1919x; 1.0066x over previous
#include <cuda_runtime.h>
#include <cuda_bf16.h>
#include <cstdint>
#include <cstddef>

#define TT  512
#define BSZ 64
#define IND 1024
#define HD  256
#define G3  768   // 3*HD

// ---------------- scratch (static __device__ — no allocations allowed) ----------------
__device__ float g_gx[(size_t)2 * TT * BSZ * G3];  // pre-activations per direction (bih folded in)
__device__ float g_ys[(size_t)2 * TT * BSZ * HD];  // per-step hidden outputs per direction

__device__ __align__(16) __nv_bfloat16 g_src_hi[(size_t)TT * BSZ * IND];
__device__ __align__(16) __nv_bfloat16 g_src_lo[(size_t)TT * BSZ * IND];
__device__ __align__(16) __nv_bfloat16 g_wih_hi[(size_t)2 * G3 * IND];
__device__ __align__(16) __nv_bfloat16 g_wih_lo[(size_t)2 * G3 * IND];

// ---------------- helpers ----------------
__device__ __forceinline__ uint32_t smem_u32(const void* p) {
    uint32_t a;
    asm("{ .reg .u64 t; cvta.to.shared.u64 t, %1; cvt.u32.u64 %0, t; }" : "=r"(a) : "l"(p));
    return a;
}

#define CP16(dst, src) \
    asm volatile("cp.async.cg.shared.global [%0], [%1], 16;" :: "r"(dst), "l"(src))
#define CP_COMMIT() asm volatile("cp.async.commit_group;" ::: "memory")
#define CP_WAIT(n)  asm volatile("cp.async.wait_group %0;" :: "n"(n) : "memory")

#define LDSM4(R, addr) \
    asm volatile("ldmatrix.sync.aligned.m8n8.x4.shared.b16 {%0,%1,%2,%3}, [%4];" \
                 : "=r"((R)[0]), "=r"((R)[1]), "=r"((R)[2]), "=r"((R)[3]) : "r"(addr))

#define MMA16816(C, A, B0, B1) \
    asm volatile("mma.sync.aligned.m16n8k16.row.col.f32.bf16.bf16.f32 " \
                 "{%0,%1,%2,%3}, {%4,%5,%6,%7}, {%8,%9}, {%0,%1,%2,%3};" \
                 : "+f"((C)[0]), "+f"((C)[1]), "+f"((C)[2]), "+f"((C)[3]) \
                 : "r"((A)[0]), "r"((A)[1]), "r"((A)[2]), "r"((A)[3]), "r"(B0), "r"(B1))

// ---------------- f32x2 packed helpers ----------------
__device__ __forceinline__ unsigned long long pk2(float x, float y) {
    unsigned long long r;
    asm("mov.b64 %0, {%1, %2};" : "=l"(r) : "f"(x), "f"(y));
    return r;
}
__device__ __forceinline__ void upk2(unsigned long long v, float& x, float& y) {
    asm("mov.b64 {%0, %1}, %2;" : "=f"(x), "=f"(y) : "l"(v));
}
__device__ __forceinline__ void ffma2(unsigned long long& d, unsigned long long a, unsigned long long b) {
    asm("fma.rn.f32x2 %0, %1, %2, %0;" : "+l"(d) : "l"(a), "l"(b));
}

// =====================================================================
// Kernel 0: split fp32 -> (hi, lo) bf16 pair. which: 0=src, 1=Wih_f, 2=Wih_b
// =====================================================================
__global__ void __launch_bounds__(256) split_bf16(const float* __restrict__ x, int which, int n)
{
    __nv_bfloat16* hi;
    __nv_bfloat16* lo;
    if (which == 0)      { hi = g_src_hi;                    lo = g_src_lo; }
    else if (which == 1) { hi = g_wih_hi;                    lo = g_wih_lo; }
    else                 { hi = g_wih_hi + (size_t)G3 * IND; lo = g_wih_lo + (size_t)G3 * IND; }

    int i = (blockIdx.x * 256 + threadIdx.x) * 4;
    if (i >= n) return;
    float4 v = *(const float4*)(x + i);
    __nv_bfloat16 h0 = __float2bfloat16_rn(v.x);
    __nv_bfloat16 h1 = __float2bfloat16_rn(v.y);
    __nv_bfloat16 h2 = __float2bfloat16_rn(v.z);
    __nv_bfloat16 h3 = __float2bfloat16_rn(v.w);
    __nv_bfloat16 l0 = __float2bfloat16_rn(v.x - __bfloat162float(h0));
    __nv_bfloat16 l1 = __float2bfloat16_rn(v.y - __bfloat162float(h1));
    __nv_bfloat16 l2 = __float2bfloat16_rn(v.z - __bfloat162float(h2));
    __nv_bfloat16 l3 = __float2bfloat16_rn(v.w - __bfloat162float(h3));
    *(__nv_bfloat162*)(hi + i)     = __nv_bfloat162(h0, h1);
    *(__nv_bfloat162*)(hi + i + 2) = __nv_bfloat162(h2, h3);
    *(__nv_bfloat162*)(lo + i)     = __nv_bfloat162(l0, l1);
    *(__nv_bfloat162*)(lo + i + 2) = __nv_bfloat162(l2, l3);
}

// =====================================================================
// Kernel A: gx via mma.sync (HMMA) bf16 split 3-MMA.
// CTA tile 128x128, K chunks of 32, cp.async double buffered.
// 16 warps as 4(m) x 4(n); warp tile 32x32 = 2x4 m16n8k16 tiles.
// 512 threads, ~90 regs/thread -> 16 warps resident, latency hidden.
// SMEM rows padded to 40 bf16 (80B) -> conflict-free ldmatrix.
// =====================================================================
#define GX_ROWB      80                  // bytes per SMEM row (40 bf16)
#define GX_MAT       (128 * GX_ROWB)     // 10240 bytes per matrix
#define GX_OFF_A_HI  0
#define GX_OFF_A_LO  (GX_MAT)
#define GX_OFF_B_HI  (2 * GX_MAT)
#define GX_OFF_B_LO  (3 * GX_MAT)
#define GX_STAGE     (4 * GX_MAT)        // 40960
#define GX_SMEM_TOTAL (2 * GX_STAGE)     // 81920

__global__ void __launch_bounds__(512) gx_mma(const float* __restrict__ bih_f,
                                              const float* __restrict__ bih_b)
{
    extern __shared__ char smem[];
    const uint32_t sbase = smem_u32(smem);
    const int tid = threadIdx.x;
    const int wid = tid >> 5;
    const int lid = tid & 31;
    const int wm  = wid >> 2;      // 0..3
    const int wn  = wid & 3;       // 0..3

    const int n0 = blockIdx.x * 128;   // n fastest -> B tiles L2-resident, A shared by 6 CTAs
    const int m0 = blockIdx.y * 128;
    const int d  = blockIdx.z;

    const __nv_bfloat16* __restrict__ whi = g_wih_hi + (size_t)d * G3 * IND;
    const __nv_bfloat16* __restrict__ wlo = g_wih_lo + (size_t)d * G3 * IND;
    const float* __restrict__ bih = d ? bih_b : bih_f;

    // ---- per-thread load mapping: row = tid&127, 16B chunk sub = tid>>7 (0..3) ----
    const int rowL = tid & 127;
    const int sub  = tid >> 7;      // 0..3
    int mA = m0 + rowL;
    int srow = d ? ((TT - 1 - (mA >> 6)) * BSZ + (mA & 63)) : mA;
    const __nv_bfloat16* gA_hi = g_src_hi + (size_t)srow * IND + sub * 8;
    const __nv_bfloat16* gA_lo = g_src_lo + (size_t)srow * IND + sub * 8;
    const __nv_bfloat16* gB_hi = whi + (size_t)(n0 + rowL) * IND + sub * 8;
    const __nv_bfloat16* gB_lo = wlo + (size_t)(n0 + rowL) * IND + sub * 8;
    const uint32_t soLoad = (uint32_t)(rowL * GX_ROWB + sub * 16);

    // ---- per-lane ldmatrix offsets ----
    const int blk = lid >> 3, rr = lid & 7;
    const uint32_t aoff = (uint32_t)(((wm * 32 + (blk & 1) * 8 + rr) * 40 + (blk >> 1) * 8) * 2);
    const uint32_t boff = (uint32_t)(((wn * 32 + (blk & 1) * 8 + rr) * 40 + (blk >> 1) * 8) * 2);

    float acc[2][4][4];
#pragma unroll
    for (int i = 0; i < 2; i++)
#pragma unroll
        for (int j = 0; j < 4; j++)
#pragma unroll
            for (int q = 0; q < 4; q++) acc[i][j][q] = 0.f;

    // ---- load chunk helper (kc: 0..31), stage in {0,1} ----
    auto load_chunk = [&](int kc, int stage) {
        const int kb = kc * 32;
        const uint32_t s0 = sbase + stage * GX_STAGE;
        CP16(s0 + GX_OFF_A_HI + soLoad, gA_hi + kb);
        CP16(s0 + GX_OFF_A_LO + soLoad, gA_lo + kb);
        CP16(s0 + GX_OFF_B_HI + soLoad, gB_hi + kb);
        CP16(s0 + GX_OFF_B_LO + soLoad, gB_lo + kb);
        CP_COMMIT();
    };

    load_chunk(0, 0);

    for (int kc = 0; kc < 32; kc++) {
        const int cur = kc & 1;
        if (kc < 31) load_chunk(kc + 1, cur ^ 1);
        if (kc < 31) { CP_WAIT(1); } else { CP_WAIT(0); }
        __syncthreads();

        const uint32_t s0 = sbase + cur * GX_STAGE;
#pragma unroll
        for (int ks = 0; ks < 2; ks++) {
            const uint32_t koff = ks * 32;   // 16 bf16 = 32 bytes
            uint32_t ah[2][4], al[2][4];
            LDSM4(ah[0], s0 + GX_OFF_A_HI + aoff + koff);
            LDSM4(ah[1], s0 + GX_OFF_A_HI + aoff + 16 * GX_ROWB + koff);
            LDSM4(al[0], s0 + GX_OFF_A_LO + aoff + koff);
            LDSM4(al[1], s0 + GX_OFF_A_LO + aoff + 16 * GX_ROWB + koff);
            uint32_t bh[2][4], bl[2][4];
#pragma unroll
            for (int p = 0; p < 2; p++) {
                LDSM4(bh[p], s0 + GX_OFF_B_HI + boff + p * 16 * GX_ROWB + koff);
                LDSM4(bl[p], s0 + GX_OFF_B_LO + boff + p * 16 * GX_ROWB + koff);
            }
#pragma unroll
            for (int tm = 0; tm < 2; tm++) {
#pragma unroll
                for (int tn = 0; tn < 4; tn++) {
                    const int p = tn >> 1, o = tn & 1;
                    MMA16816(acc[tm][tn], ah[tm], bh[p][o], bh[p][2 + o]);
                    MMA16816(acc[tm][tn], ah[tm], bl[p][o], bl[p][2 + o]);
                    MMA16816(acc[tm][tn], al[tm], bh[p][o], bh[p][2 + o]);
                }
            }
        }
        __syncthreads();
    }

    // ---- epilogue: direct register -> global stores, bias folded ----
    const int g  = lid >> 2;
    const int t4 = lid & 3;
    const size_t dbase = (size_t)d * TT * BSZ;
#pragma unroll
    for (int tm = 0; tm < 2; tm++) {
        int mr = m0 + wm * 32 + tm * 16 + g;
#pragma unroll
        for (int tn = 0; tn < 4; tn++) {
            int col = n0 + wn * 32 + tn * 8 + t4 * 2;
            float2 bv = *(const float2*)(bih + col);
            float2 v0 = make_float2(acc[tm][tn][0] + bv.x, acc[tm][tn][1] + bv.y);
            float2 v1 = make_float2(acc[tm][tn][2] + bv.x, acc[tm][tn][3] + bv.y);
            *(float2*)(g_gx + (dbase + mr) * G3 + col)     = v0;
            *(float2*)(g_gx + (dbase + mr + 8) * G3 + col) = v1;
        }
    }
}

// =====================================================================
// Kernel B: GRU recurrence, persistent cluster kernel (unchanged).
// =====================================================================
__global__ void __launch_bounds__(256, 1) __cluster_dims__(8, 1, 1)
gru_rec(const float* __restrict__ Whh_f, const float* __restrict__ bhh_f,
        const float* __restrict__ Whh_b, const float* __restrict__ bhh_b)
{
    __shared__ float h_sm[2][8][HD];
    __shared__ float red[8][8][3][32];

    const int rank = blockIdx.x & 7;
    const int cid  = blockIdx.x >> 3;
    const int d    = cid >> 3;
    const int bg   = cid & 7;

    const float* __restrict__ Whh = d ? Whh_b : Whh_f;
    const float* __restrict__ bhh = d ? bhh_b : bhh_f;

    const int tid = threadIdx.x;
    const int w   = tid >> 5;
    const int l   = tid & 31;
    const int j   = rank * 32 + l;
    const int kb  = w * 32;

    unsigned long long Wr[16], Wz[16], Wn[16];
#pragma unroll
    for (int q = 0; q < 16; q++) {
        Wr[q] = *(const unsigned long long*)(Whh + (size_t)j * HD + kb + 2 * q);
        Wz[q] = *(const unsigned long long*)(Whh + (size_t)(HD + j) * HD + kb + 2 * q);
        Wn[q] = *(const unsigned long long*)(Whh + (size_t)(2 * HD + j) * HD + kb + 2 * q);
    }
    const float br = bhh[j], bz = bhh[HD + j], bn = bhh[2 * HD + j];

    size_t gx_ix = ((size_t)d * TT * BSZ + (size_t)(bg * 8 + w)) * G3 + j;
    size_t ys_ix = ((size_t)d * TT * BSZ + (size_t)(bg * 8 + w)) * HD + j;

    for (int i = tid; i < 8 * HD; i += 256) (&h_sm[0][0][0])[i] = 0.f;
    __syncthreads();
    asm volatile("barrier.cluster.arrive.aligned;" ::: "memory");
    asm volatile("barrier.cluster.wait.aligned;" ::: "memory");

    uint32_t haddr_base;
    asm("{ .reg .u64 t; cvta.to.shared.u64 t, %1; cvt.u32.u64 %0, t; }"
        : "=r"(haddr_base) : "l"(&h_sm[0][0][0]));

    int cur = 0;
    for (int t = 0; t < TT; ++t) {
        float gxr = g_gx[gx_ix];
        float gxz = g_gx[gx_ix + HD];
        float gxn = g_gx[gx_ix + 2 * HD];

#pragma unroll 1
        for (int b = 0; b < 8; b++) {
            const ulonglong2* hp = (const ulonglong2*)&h_sm[cur][b][kb];
            unsigned long long ar0 = 0, ar1 = 0, az0 = 0, az1 = 0, an0 = 0, an1 = 0;
#pragma unroll
            for (int q = 0; q < 8; q++) {
                ulonglong2 hv = hp[q];
                ffma2(ar0, Wr[2 * q], hv.x); ffma2(ar1, Wr[2 * q + 1], hv.y);
                ffma2(az0, Wz[2 * q], hv.x); ffma2(az1, Wz[2 * q + 1], hv.y);
                ffma2(an0, Wn[2 * q], hv.x); ffma2(an1, Wn[2 * q + 1], hv.y);
            }
            float x0, y0, x1, y1;
            upk2(ar0, x0, y0); upk2(ar1, x1, y1); red[w][b][0][l] = x0 + y0 + x1 + y1;
            upk2(az0, x0, y0); upk2(az1, x1, y1); red[w][b][1][l] = x0 + y0 + x1 + y1;
            upk2(an0, x0, y0); upk2(an1, x1, y1); red[w][b][2][l] = x0 + y0 + x1 + y1;
        }
        __syncthreads();

        float sr = br, sz = bz, sn = bn;
#pragma unroll
        for (int w2 = 0; w2 < 8; w2++) {
            sr += red[w2][w][0][l];
            sz += red[w2][w][1][l];
            sn += red[w2][w][2][l];
        }
        float r = 1.f / (1.f + expf(-(gxr + sr)));
        float z = 1.f / (1.f + expf(-(gxz + sz)));
        float n = tanhf(gxn + r * sn);
        float hprev = h_sm[cur][w][j];
        float hnew  = n + z * (hprev - n);

        g_ys[ys_ix] = hnew;

        uint32_t la = haddr_base + (uint32_t)((((cur ^ 1) * 8 + w) * HD + j) * 4);
#pragma unroll
        for (int p = 0; p < 8; p++) {
            uint32_t ra;
            asm volatile("mapa.shared::cluster.u32 %0, %1, %2;" : "=r"(ra) : "r"(la), "r"(p));
            asm volatile("st.shared::cluster.f32 [%0], %1;" :: "r"(ra), "f"(hnew) : "memory");
        }
        asm volatile("barrier.cluster.arrive.aligned;" ::: "memory");
        asm volatile("barrier.cluster.wait.aligned;" ::: "memory");

        cur ^= 1;
        gx_ix += (size_t)BSZ * G3;
        ys_ix += (size_t)BSZ * HD;
    }
}

// =====================================================================
// Kernel C: outputs GEMM (fp32 FFMA2, unchanged)
// =====================================================================
__global__ void __launch_bounds__(256) out_gemm(
    const float* __restrict__ Wout, const float* __restrict__ bout,
    float* __restrict__ out)
{
    const int m0 = blockIdx.x * 128;
    const int n0 = blockIdx.y * 64;

    __shared__ float As[16][132];
    __shared__ float Bs[16][68];

    const int tid = threadIdx.x;
    const int tx = tid & 7;
    const int ty = tid >> 3;

    unsigned long long acc[4][4];
#pragma unroll
    for (int i = 0; i < 4; i++)
#pragma unroll
        for (int j = 0; j < 4; j++) acc[i][j] = 0ull;

    for (int kt = 0; kt < 2 * HD; kt += 16) {
#pragma unroll
        for (int i = 0; i < 2; i++) {
            int idx = tid + i * 256;
            int mi = idx >> 2, ki = (idx & 3) << 2;
            int m = m0 + mi;
            size_t aoff;
            if (kt < HD) {
                aoff = (size_t)m * HD + kt + ki;
            } else {
                int tt = m >> 6, bb = m & 63;
                aoff = (size_t)TT * BSZ * HD +
                       ((size_t)(TT - 1 - tt) * BSZ + bb) * HD + (kt + ki - HD);
            }
            float4 v = *(const float4*)(g_ys + aoff);
            As[ki + 0][mi] = v.x; As[ki + 1][mi] = v.y;
            As[ki + 2][mi] = v.z; As[ki + 3][mi] = v.w;
        }
        {
            int ni = tid >> 2, ki = (tid & 3) << 2;
            float4 wv = *(const float4*)(Wout + (size_t)(n0 + ni) * (2 * HD) + kt + ki);
            Bs[ki + 0][ni] = wv.x; Bs[ki + 1][ni] = wv.y;
            Bs[ki + 2][ni] = wv.z; Bs[ki + 3][ni] = wv.w;
        }
        __syncthreads();
#pragma unroll
        for (int k = 0; k < 16; k++) {
            float4 a0 = *(const float4*)&As[k][ty * 4];
            ulonglong2 b0 = *(const ulonglong2*)&Bs[k][tx * 8];
            ulonglong2 b1 = *(const ulonglong2*)&Bs[k][tx * 8 + 4];
            float a[4] = {a0.x, a0.y, a0.z, a0.w};
            unsigned long long bb2[4] = {b0.x, b0.y, b1.x, b1.y};
#pragma unroll
            for (int i = 0; i < 4; i++) {
                unsigned long long ad = pk2(a[i], a[i]);
#pragma unroll
                for (int j = 0; j < 4; j++) ffma2(acc[i][j], ad, bb2[j]);
            }
        }
        __syncthreads();
    }

#pragma unroll
    for (int i = 0; i < 4; i++) {
        int m = m0 + ty * 4 + i;
        float* op = out + (size_t)m * HD + n0 + tx * 8;
#pragma unroll
        for (int j = 0; j < 4; j++) {
            float x, y;
            upk2(acc[i][j], x, y);
            int n = n0 + tx * 8 + j * 2;
            float2 o = make_float2(x + bout[n], y + bout[n + 1]);
            *(float2*)(op + j * 2) = o;
        }
    }
}

// =====================================================================
// Kernel D: hidden projection (unchanged)
// =====================================================================
__global__ void __launch_bounds__(256) hid_kernel(
    const float* __restrict__ Whid, const float* __restrict__ bhid,
    float* __restrict__ hid)
{
    const int b = blockIdx.x;
    const int o = threadIdx.x;
    __shared__ float hc[2 * HD];
    for (int k = threadIdx.x; k < 2 * HD; k += 256) {
        hc[k] = (k < HD)
            ? g_ys[((size_t)(TT - 1) * BSZ + b) * HD + k]
            : g_ys[(size_t)TT * BSZ * HD + ((size_t)(TT - 1) * BSZ + b) * HD + (k - HD)];
    }
    __syncthreads();
    float acc = bhid[o];
    const float4* wp = (const float4*)(Whid + (size_t)o * (2 * HD));
    const float4* hp = (const float4*)hc;
#pragma unroll 4
    for (int q = 0; q < (2 * HD) / 4; q++) {
        float4 wv = wp[q], hv = hp[q];
        acc += wv.x * hv.x + wv.y * hv.y + wv.z * hv.z + wv.w * hv.w;
    }
    hid[(size_t)b * HD + o] = tanhf(acc);
}

// =====================================================================
extern "C" void kernel_launch(void* const* d_in, const int* in_sizes, int n_in,
                              void* d_out, int out_size)
{
    const float* src   = (const float*)d_in[0];
    const float* Wih_f = (const float*)d_in[1];
    const float* Whh_f = (const float*)d_in[2];
    const float* bih_f = (const float*)d_in[3];
    const float* bhh_f = (const float*)d_in[4];
    const float* Wih_b = (const float*)d_in[5];
    const float* Whh_b = (const float*)d_in[6];
    const float* bih_b = (const float*)d_in[7];
    const float* bhh_b = (const float*)d_in[8];
    const float* Wout  = (const float*)d_in[9];
    const float* bout  = (const float*)d_in[10];
    const float* Whid  = (const float*)d_in[11];
    const float* bhid  = (const float*)d_in[12];
    float* out = (float*)d_out;

    cudaFuncSetAttribute(gx_mma, cudaFuncAttributeMaxDynamicSharedMemorySize, GX_SMEM_TOTAL);

    {
        int n_src = TT * BSZ * IND;
        int n_w   = G3 * IND;
        split_bf16<<<(n_src / 4 + 255) / 256, 256>>>(src, 0, n_src);
        split_bf16<<<(n_w   / 4 + 255) / 256, 256>>>(Wih_f, 1, n_w);
        split_bf16<<<(n_w   / 4 + 255) / 256, 256>>>(Wih_b, 2, n_w);
    }

    gx_mma<<<dim3(G3 / 128, TT * BSZ / 128, 2), 512, GX_SMEM_TOTAL>>>(bih_f, bih_b);
    gru_rec<<<128, 256>>>(Whh_f, bhh_f, Whh_b, bhh_b);
    out_gemm<<<dim3(TT * BSZ / 128, HD / 64), 256>>>(Wout, bout, out);
    hid_kernel<<<BSZ, 256>>>(Whid, bhid, out + (size_t)TT * BSZ * HD);
}